// round 6
// baseline (speedup 1.0000x reference)
#include <cuda_runtime.h>

#define T_TOKENS 16384
#define H_DIM    2880
#define E_EXP    32
#define TOPK     4
#define BM       128
#define BK       32
#define KSPLIT   3
#define NT       30              // k-tiles per split (90/3)
#define NTHREADS 128
#define XS       36              // smem row stride (floats)
#define NROWS    160             // 128 x-rows + 32 w-rows

typedef unsigned long long u64;

__device__ float g_scratch[KSPLIT][T_TOKENS][E_EXP];   // 6 MB partial logits

__device__ __forceinline__ u64 ffma2(u64 a, u64 b, u64 c) {
    u64 d;
    asm("fma.rn.f32x2 %0, %1, %2, %3;" : "=l"(d) : "l"(a), "l"(b), "l"(c));
    return d;
}
__device__ __forceinline__ unsigned smem_u32(const void* p) {
    return (unsigned)__cvta_generic_to_shared(p);
}
__device__ __forceinline__ void cp16(unsigned dst, const void* src) {
    asm volatile("cp.async.cg.shared.global [%0], [%1], 16;" :: "r"(dst), "l"(src));
}
__device__ __forceinline__ void cp_commit() {
    asm volatile("cp.async.commit_group;");
}
template <int N>
__device__ __forceinline__ void cp_wait() {
    asm volatile("cp.async.wait_group %0;" :: "n"(N));
}
__device__ __forceinline__ float hadd2(u64 v) {
    float lo, hi;
    asm("mov.b64 {%0, %1}, %2;" : "=f"(lo), "=f"(hi) : "l"(v));
    return lo + hi;
}

// ---------------- kernel 1: split-K partial GEMM ----------------
__global__ __launch_bounds__(NTHREADS, 3)
void gate_partial(const float* __restrict__ x,
                  const float* __restrict__ w)
{
    // 3-stage pipeline. rows 0..127 = x tokens, 128..159 = w experts. K-major, f32x2 pairs along K.
    __shared__ __align__(16) float buf[3][NROWS][XS];   // 69120 B

    const int tid   = threadIdx.x;
    const int tb    = blockIdx.x;        // token block 0..127
    const int split = blockIdx.y;        // 0..2
    const int t0    = tb * BM;
    const int kbase = split * NT * BK;

    const int lane = tid & 31;
    const int warp = tid >> 5;
    const int r    = lane >> 3;          // 0..3
    const int c    = lane & 7;           // 0..7
    const int wtok = warp * 32;          // warp's 32 tokens

    // prefetch mapping: prow 0..15, pcol 0..7; x rows prow+16i (i<8); w rows prow+16i (i<2)
    const int prow = tid >> 3;
    const int pcol = tid & 7;
    const float* xsrc = x + (size_t)(t0 + prow) * H_DIM + kbase + pcol * 4;
    const float* wsrc = w + (size_t)prow * H_DIM + kbase + pcol * 4;

    // acc[i][j]: f32x2 partials for token wtok+r+4i (i<8), expert c+8j (j<4)
    u64 acc[8][4];
    #pragma unroll
    for (int i = 0; i < 8; ++i)
        #pragma unroll
        for (int j = 0; j < 4; ++j) acc[i][j] = 0ull;

    auto prefetch = [&](int kt, int b) {
        const size_t k0 = (size_t)kt * BK;
        #pragma unroll
        for (int i = 0; i < 8; ++i)
            cp16(smem_u32(&buf[b][prow + 16 * i][pcol * 4]),
                 xsrc + k0 + (size_t)(16 * i) * H_DIM);
        #pragma unroll
        for (int i = 0; i < 2; ++i)
            cp16(smem_u32(&buf[b][128 + prow + 16 * i][pcol * 4]),
                 wsrc + k0 + (size_t)(16 * i) * H_DIM);
        cp_commit();
    };

    prefetch(0, 0);
    prefetch(1, 1);

    for (int kt = 0; kt < NT; ++kt) {
        if (kt + 1 < NT) { cp_wait<1>(); } else { cp_wait<0>(); }
        __syncthreads();                       // tile kt visible; prev compute done
        if (kt + 2 < NT) prefetch(kt + 2, (kt + 2) % 3);   // safe: targets buf != kt%3, (kt+1)%3

        const float (*tb_)[XS] = buf[kt % 3];

        #pragma unroll
        for (int kq = 0; kq < 8; ++kq) {
            ulonglong2 a[8], b[4];
            #pragma unroll
            for (int i = 0; i < 8; ++i)
                a[i] = *reinterpret_cast<const ulonglong2*>(&tb_[wtok + r + 4 * i][kq * 4]);
            #pragma unroll
            for (int j = 0; j < 4; ++j)
                b[j] = *reinterpret_cast<const ulonglong2*>(&tb_[128 + c + 8 * j][kq * 4]);

            #pragma unroll
            for (int i = 0; i < 8; ++i)
                #pragma unroll
                for (int j = 0; j < 4; ++j)
                    acc[i][j] = ffma2(a[i].x, b[j].x, acc[i][j]);
            #pragma unroll
            for (int i = 0; i < 8; ++i)
                #pragma unroll
                for (int j = 0; j < 4; ++j)
                    acc[i][j] = ffma2(a[i].y, b[j].y, acc[i][j]);
        }
    }
    __syncthreads();   // all compute done before smem reuse

    // stage partial logits in smem, then coalesced store to scratch
    float (*lg)[E_EXP + 1] = reinterpret_cast<float (*)[E_EXP + 1]>(&buf[0][0][0]);
    #pragma unroll
    for (int i = 0; i < 8; ++i)
        #pragma unroll
        for (int j = 0; j < 4; ++j)
            lg[wtok + r + 4 * i][c + 8 * j] = hadd2(acc[i][j]);
    __syncthreads();

    {
        float* dst = &g_scratch[split][t0 + tid][0];
        #pragma unroll
        for (int q = 0; q < 8; ++q) {
            float4 v = make_float4(lg[tid][4 * q], lg[tid][4 * q + 1],
                                   lg[tid][4 * q + 2], lg[tid][4 * q + 3]);
            *reinterpret_cast<float4*>(dst + 4 * q) = v;
        }
    }
}

// ---------------- kernel 2: reduce + bias + top-4 + softmax ----------------
__global__ __launch_bounds__(256)
void gate_reduce(const float* __restrict__ bias, float* __restrict__ out)
{
    const int t = blockIdx.x * 256 + threadIdx.x;

    float la[E_EXP];
    #pragma unroll
    for (int q = 0; q < 8; ++q) {
        float4 v = *reinterpret_cast<const float4*>(&g_scratch[0][t][4 * q]);
        la[4 * q] = v.x; la[4 * q + 1] = v.y; la[4 * q + 2] = v.z; la[4 * q + 3] = v.w;
    }
    #pragma unroll
    for (int s = 1; s < KSPLIT; ++s) {
        #pragma unroll
        for (int q = 0; q < 8; ++q) {
            float4 v = *reinterpret_cast<const float4*>(&g_scratch[s][t][4 * q]);
            la[4 * q] += v.x; la[4 * q + 1] += v.y; la[4 * q + 2] += v.z; la[4 * q + 3] += v.w;
        }
    }

    float bv0 = -1e30f, bv1 = -1e30f, bv2 = -1e30f, bv3 = -1e30f;
    int   bi0 = 0, bi1 = 0, bi2 = 0, bi3 = 0;
    #pragma unroll
    for (int e = 0; e < E_EXP; ++e) {
        float lv = la[e] + bias[e];
        if (lv > bv3) {
            if (lv > bv0) {
                bv3 = bv2; bi3 = bi2; bv2 = bv1; bi2 = bi1; bv1 = bv0; bi1 = bi0;
                bv0 = lv;  bi0 = e;
            } else if (lv > bv1) {
                bv3 = bv2; bi3 = bi2; bv2 = bv1; bi2 = bi1;
                bv1 = lv;  bi1 = e;
            } else if (lv > bv2) {
                bv3 = bv2; bi3 = bi2;
                bv2 = lv;  bi2 = e;
            } else {
                bv3 = lv;  bi3 = e;
            }
        }
    }
    float e0 = 1.0f;
    float e1 = expf(bv1 - bv0);
    float e2 = expf(bv2 - bv0);
    float e3 = expf(bv3 - bv0);
    float inv = 1.0f / (e0 + e1 + e2 + e3);

    float* oi = out + (size_t)t * TOPK;
    float* ow = out + (size_t)T_TOKENS * TOPK + (size_t)t * TOPK;
    oi[0] = (float)bi0; oi[1] = (float)bi1; oi[2] = (float)bi2; oi[3] = (float)bi3;
    ow[0] = e0 * inv;   ow[1] = e1 * inv;   ow[2] = e2 * inv;   ow[3] = e3 * inv;
}

extern "C" void kernel_launch(void* const* d_in, const int* in_sizes, int n_in,
                              void* d_out, int out_size)
{
    const float* x    = (const float*)d_in[0];  // [4,4096,2880] f32
    const float* w    = (const float*)d_in[1];  // [32,2880] f32
    const float* bias = (const float*)d_in[2];  // [32] f32
    float* out = (float*)d_out;

    dim3 grid1(T_TOKENS / BM, KSPLIT);          // 128 x 3 = 384 CTAs
    gate_partial<<<grid1, NTHREADS>>>(x, w);
    gate_reduce<<<T_TOKENS / 256, 256>>>(bias, out);
}